// round 3
// baseline (speedup 1.0000x reference)
#include <cuda_runtime.h>
#include <math.h>

#define MAXD 2048
#define ETA 0.005f

// Scratch for the per-column and per-row reductions (no allocation allowed).
__device__ float g_m[MAXD];       // m[j] = mean_b x[b,j]*x[j,b]
__device__ float g_rmean[MAXD];   // rowmean[b] = mean_j x[b,j]

// ---------------------------------------------------------------------------
// Kernel 1: per-block handles 4 consecutive columns j0..j0+3.
//   Phase A: load rows j0..j0+3 into shared (coalesced) -> rowmean[j0..j0+3]
//   Phase B: sweep b, one float4 load x[b][j0..j0+3] per thread (full-sector
//            column reads), multiply with staged transpose values.
// ---------------------------------------------------------------------------
__global__ void __launch_bounds__(256) hebb_reduce_kernel(
    const float* __restrict__ x, int D)
{
    __shared__ float srow[4][MAXD];
    __shared__ float red_m[4];
    __shared__ float red_r[4];

    const int tid = threadIdx.x;
    const int j0  = blockIdx.x * 4;

    if (tid < 4) { red_m[tid] = 0.0f; red_r[tid] = 0.0f; }
    __syncthreads();

    const int D4 = D >> 2;

    // Phase A: stage 4 rows, accumulate row sums.
    #pragma unroll
    for (int r = 0; r < 4; r++) {
        const float4* rowp = reinterpret_cast<const float4*>(x + (size_t)(j0 + r) * D);
        float s = 0.0f;
        for (int c4 = tid; c4 < D4; c4 += 256) {
            float4 v = rowp[c4];
            reinterpret_cast<float4*>(srow[r])[c4] = v;
            s += (v.x + v.y) + (v.z + v.w);
        }
        #pragma unroll
        for (int o = 16; o > 0; o >>= 1)
            s += __shfl_xor_sync(0xFFFFFFFFu, s, o);
        if ((tid & 31) == 0) atomicAdd(&red_r[r], s);
    }
    __syncthreads();

    // Phase B: column sweep. Thread t handles rows b = t, t+256, ...
    // Unrolled x4 so ptxas front-batches the column loads (MLP for latency hiding).
    float acc0 = 0.0f, acc1 = 0.0f, acc2 = 0.0f, acc3 = 0.0f;
    const float* xcol = x + j0;
    #pragma unroll 4
    for (int b = tid; b < D; b += 256) {
        float4 v = *reinterpret_cast<const float4*>(xcol + (size_t)b * D);
        acc0 += v.x * srow[0][b];
        acc1 += v.y * srow[1][b];
        acc2 += v.z * srow[2][b];
        acc3 += v.w * srow[3][b];
    }
    #pragma unroll
    for (int o = 16; o > 0; o >>= 1) {
        acc0 += __shfl_xor_sync(0xFFFFFFFFu, acc0, o);
        acc1 += __shfl_xor_sync(0xFFFFFFFFu, acc1, o);
        acc2 += __shfl_xor_sync(0xFFFFFFFFu, acc2, o);
        acc3 += __shfl_xor_sync(0xFFFFFFFFu, acc3, o);
    }
    if ((tid & 31) == 0) {
        atomicAdd(&red_m[0], acc0);
        atomicAdd(&red_m[1], acc1);
        atomicAdd(&red_m[2], acc2);
        atomicAdd(&red_m[3], acc3);
    }
    __syncthreads();

    if (tid < 4) {
        const float inv = 1.0f / (float)D;
        g_m[j0 + tid]     = red_m[tid] * inv;
        g_rmean[j0 + tid] = red_r[tid] * inv;
    }
}

// ---------------------------------------------------------------------------
// Kernel 2: elementwise outputs.
//   y[i,j]  = kernel[i,j] * m[j]                       (LMBDA = 1)
//   nk[i,j] = kernel[i,j] + ETA * x[i,j] * rowmean[i]
// ---------------------------------------------------------------------------
__global__ void __launch_bounds__(256) hebb_ew_kernel(
    const float* __restrict__ x, const float* __restrict__ kmat,
    float* __restrict__ y, float* __restrict__ nk,
    int D, int n4, int write_nk)
{
    int idx = blockIdx.x * 256 + threadIdx.x;
    if (idx >= n4) return;

    const int D4   = D >> 2;
    const int col4 = idx % D4;   // float4 column index
    const int row  = idx / D4;

    float4 kv = reinterpret_cast<const float4*>(kmat)[idx];
    float4 mv = reinterpret_cast<const float4*>(g_m)[col4];

    float4 yv;
    yv.x = kv.x * mv.x;
    yv.y = kv.y * mv.y;
    yv.z = kv.z * mv.z;
    yv.w = kv.w * mv.w;
    reinterpret_cast<float4*>(y)[idx] = yv;

    if (write_nk) {
        float rm = __ldg(&g_rmean[row]) * ETA;
        float4 xv = reinterpret_cast<const float4*>(x)[idx];
        float4 nkv;
        nkv.x = fmaf(rm, xv.x, kv.x);
        nkv.y = fmaf(rm, xv.y, kv.y);
        nkv.z = fmaf(rm, xv.z, kv.z);
        nkv.w = fmaf(rm, xv.w, kv.w);
        reinterpret_cast<float4*>(nk)[idx] = nkv;
    }
}

extern "C" void kernel_launch(void* const* d_in, const int* in_sizes, int n_in,
                              void* d_out, int out_size)
{
    if (n_in < 2 || !d_in || !d_out || !in_sizes) return;

    const float* x    = (const float*)d_in[0];
    const float* kmat = (const float*)d_in[1];
    float* out        = (float*)d_out;

    const int n = in_sizes[0];           // D*D
    int D = 1;
    while (D < MAXD && D * D < n) D++;   // D = 2048 for this problem
    if (D * D != n || (D & 3) != 0) return;

    const int n4 = n >> 2;
    const int write_nk = (out_size >= 2 * n) ? 1 : 0;

    float* y  = out;
    float* nk = out + n;                 // second output region (if present)

    hebb_reduce_kernel<<<D / 4, 256>>>(x, D);
    hebb_ew_kernel<<<(n4 + 255) / 256, 256>>>(x, kmat, y, nk, D, n4, write_nk);
}

// round 5
// speedup vs baseline: 1.3106x; 1.3106x over previous
#include <cuda_runtime.h>
#include <math.h>

#define MAXD 2048
#define TILE 64
#define ETA 0.005f

// Accumulators (atomically updated; zeroed at the start of every launch).
__device__ float g_m[MAXD];   // sum_b x[b,j]*x[j,b]   (scaled by 1/D at use)
__device__ float g_r[MAXD];   // sum_j x[b,j]          (scaled by 1/D at use)

// ---------------------------------------------------------------------------
// Kernel 0: zero the accumulators (required for graph replays).
// ---------------------------------------------------------------------------
__global__ void hebb_zero_kernel(int D)
{
    int i = blockIdx.x * blockDim.x + threadIdx.x;
    if (i < D) { g_m[i] = 0.0f; g_r[i] = 0.0f; }
}

// ---------------------------------------------------------------------------
// Kernel 1: symmetric tile-pair reduction. Block handles unordered {I,J},
// I <= J, reading tiles A = x[I-tile, J-tile], B = x[J-tile, I-tile] ONCE
// (coalesced). P[u,v] = A[u][v]*B[v][u].
//   col-sums of P  -> m[J*64 + v]      row-sums of P -> m[I*64 + u]
//   row-sums of B  -> r[J*64 + v]      row-sums of A -> r[I*64 + u]
// Diagonal blocks (I==J): pass 1 only (covers all (b,j) pairs once).
// ---------------------------------------------------------------------------
__global__ void __launch_bounds__(256) hebb_tile_kernel(
    const float* __restrict__ x, int D, int NT)
{
    __shared__ float A[TILE][TILE + 1];
    __shared__ float B[TILE][TILE + 1];
    __shared__ float redM[4][TILE];
    __shared__ float redR[4][TILE];

    // Invert triangular index: bid -> (I, J), I <= J, row-major upper.
    const int t = blockIdx.x;
    const float fN = 2.0f * (float)NT + 1.0f;
    int I = (int)((fN - sqrtf(fN * fN - 8.0f * (float)t)) * 0.5f);
    #define TRI_BASE(i) ((i) * NT - ((i) * ((i) - 1)) / 2)
    while (I > 0 && TRI_BASE(I) > t) I--;
    while (TRI_BASE(I + 1) <= t) I++;
    const int J = I + (t - TRI_BASE(I));
    #undef TRI_BASE

    const int tid = threadIdx.x;
    const int r   = tid >> 2;          // 0..63  (row within tile)
    const int cg  = (tid & 3) << 4;    // 0,16,32,48 (col group)
    const bool diag = (I == J);

    // Load A (coalesced: warp covers 8 rows x 64 consecutive floats).
    {
        const float* ap = x + (size_t)(I * TILE + r) * D + J * TILE + cg;
        #pragma unroll
        for (int k = 0; k < 16; k += 4) {
            float4 v = *reinterpret_cast<const float4*>(ap + k);
            A[r][cg + k + 0] = v.x; A[r][cg + k + 1] = v.y;
            A[r][cg + k + 2] = v.z; A[r][cg + k + 3] = v.w;
        }
    }
    if (!diag) {
        const float* bp = x + (size_t)(J * TILE + r) * D + I * TILE + cg;
        #pragma unroll
        for (int k = 0; k < 16; k += 4) {
            float4 v = *reinterpret_cast<const float4*>(bp + k);
            B[r][cg + k + 0] = v.x; B[r][cg + k + 1] = v.y;
            B[r][cg + k + 2] = v.z; B[r][cg + k + 3] = v.w;
        }
    }
    __syncthreads();

    float (*Bt)[TILE + 1] = diag ? A : B;

    // Pass 1: per-column v; group g sums rows u0..u0+15.
    {
        const int v  = tid & 63;
        const int g  = tid >> 6;
        const int u0 = g << 4;
        float am = 0.0f, ar = 0.0f;
        #pragma unroll
        for (int k = 0; k < 16; k++) {
            const int u = u0 + k;
            const float bvu = Bt[v][u];      // stride-65 across lanes: conflict-free
            am += A[u][v] * bvu;             // stride-1 across lanes: conflict-free
            ar += bvu;
        }
        redM[g][v] = am;
        redR[g][v] = ar;
    }
    __syncthreads();
    if (tid < 64) {
        float sm = redM[0][tid] + redM[1][tid] + redM[2][tid] + redM[3][tid];
        float sr = redR[0][tid] + redR[1][tid] + redR[2][tid] + redR[3][tid];
        atomicAdd(&g_m[J * TILE + tid], sm);
        atomicAdd(&g_r[J * TILE + tid], sr);
    }
    if (diag) return;
    __syncthreads();

    // Pass 2: per-row u; group g sums cols v0..v0+15.
    {
        const int u  = tid & 63;
        const int g  = tid >> 6;
        const int v0 = g << 4;
        float am = 0.0f, ar = 0.0f;
        #pragma unroll
        for (int k = 0; k < 16; k++) {
            const int v = v0 + k;
            const float auv = A[u][v];
            am += auv * B[v][u];
            ar += auv;
        }
        redM[g][u] = am;
        redR[g][u] = ar;
    }
    __syncthreads();
    if (tid < 64) {
        float sm = redM[0][tid] + redM[1][tid] + redM[2][tid] + redM[3][tid];
        float sr = redR[0][tid] + redR[1][tid] + redR[2][tid] + redR[3][tid];
        atomicAdd(&g_m[I * TILE + tid], sm);
        atomicAdd(&g_r[I * TILE + tid], sr);
    }
}

// ---------------------------------------------------------------------------
// Kernel 2: one block per row, 512 threads, one float4 per thread per iter.
//   y[i,j]  = kernel[i,j] * (m[j]/D)
//   nk[i,j] = kernel[i,j] + (ETA*rowmean[i]/D) * x[i,j]
// No div/mod; rmean is one broadcast load per block.
// ---------------------------------------------------------------------------
__global__ void __launch_bounds__(512) hebb_ew_kernel(
    const float* __restrict__ x, const float* __restrict__ kmat,
    float* __restrict__ y, float* __restrict__ nk,
    int D4, float invD, int write_nk)
{
    const int row = blockIdx.x;
    const size_t base = (size_t)row * D4;

    const float rm = g_r[row] * (invD * ETA);

    const float4* k4 = reinterpret_cast<const float4*>(kmat) + base;
    const float4* x4 = reinterpret_cast<const float4*>(x) + base;
    const float4* m4 = reinterpret_cast<const float4*>(g_m);
    float4* y4  = reinterpret_cast<float4*>(y) + base;
    float4* nk4 = reinterpret_cast<float4*>(nk) + base;

    for (int c = threadIdx.x; c < D4; c += 512) {
        float4 kv = k4[c];
        float4 mv = m4[c];
        float4 yv;
        yv.x = kv.x * (mv.x * invD);
        yv.y = kv.y * (mv.y * invD);
        yv.z = kv.z * (mv.z * invD);
        yv.w = kv.w * (mv.w * invD);
        y4[c] = yv;
        if (write_nk) {
            float4 xv = x4[c];
            float4 nv;
            nv.x = fmaf(rm, xv.x, kv.x);
            nv.y = fmaf(rm, xv.y, kv.y);
            nv.z = fmaf(rm, xv.z, kv.z);
            nv.w = fmaf(rm, xv.w, kv.w);
            nk4[c] = nv;
        }
    }
}

extern "C" void kernel_launch(void* const* d_in, const int* in_sizes, int n_in,
                              void* d_out, int out_size)
{
    if (n_in < 2 || !d_in || !d_out || !in_sizes) return;

    const float* x    = (const float*)d_in[0];
    const float* kmat = (const float*)d_in[1];
    float* out        = (float*)d_out;

    const int n = in_sizes[0];           // D*D
    int D = 1;
    while (D < MAXD && D * D < n) D++;   // D = 2048 here
    if (D * D != n || (D % TILE) != 0) return;

    const int NT = D / TILE;              // 32
    const int nPairs = NT * (NT + 1) / 2; // 528
    const int write_nk = (out_size >= 2 * n) ? 1 : 0;
    const float invD = 1.0f / (float)D;

    float* y  = out;
    float* nk = out + n;

    hebb_zero_kernel<<<(D + 1023) / 1024, 1024>>>(D);
    hebb_tile_kernel<<<nPairs, 256>>>(x, D, NT);
    hebb_ew_kernel<<<D, 512>>>(x, kmat, y, nk, D >> 2, invD, write_nk);
}